// round 15
// baseline (speedup 1.0000x reference)
#include <cuda_runtime.h>
#include <cuda_bf16.h>

// Problem constants: nw_out is [N=4, C=19, H=512, W=1024] float32.
#define NCH    19
#define NBAT   4
#define HH     512
#define WW     1024
#define HWP    (HH * WW)            // 524288 pixels per image
#define HWP2   (HWP / 2)            // 262144 float2 pairs per image-channel
#define NPIX   (NBAT * HWP)         // 2097152
#define NPAIR  (NPIX / 2)           // 1048576
#define IW_F   0.2f
#define GRID_BLOCKS 740             // 5 CTAs/SM x 148 SMs = one wave

// Fixed-point packing: bits [0,42) = sum(r * 2^20), bits [42,64) = count.
// Worst case one class: sum <= 2^21 * 2^20 = 2^41 < 2^42, cnt <= 2^21. No overflow.
#define R_SCALE   1048576.0f        // 2^20
#define CNT_ONE   (1ULL << 42)
#define SUM_MASK  (CNT_ONE - 1ULL)

// Per-CTA-distinct bins: REDG lands in L2 atomic ALUs (0.854-1.29 cyc/lane,
// spread over 14060 addresses) instead of the SM's LSU (2 cyc/lane ATOMS).
// Zeroed at module load; the fused finalize re-zeroes after consuming.
__device__ unsigned long long g_bins[NCH][GRID_BLOCKS] = {};
__device__ unsigned int       g_done = 0;

__global__ __launch_bounds__(256, 5) void msiw_kernel(const float2* __restrict__ x2,
                                                      float* __restrict__ out) {
    const int t = threadIdx.x;
    // Packed log2(e) constant for the exp conversion (hoisted).
    unsigned long long L2E2;
    asm("mov.b64 %0, {%1, %2};" : "=l"(L2E2)
        : "f"(1.4426950408889634f), "f"(1.4426950408889634f));

    const int stride = GRID_BLOCKS * 256;          // in float2 pairs
    for (int q = blockIdx.x * blockDim.x + t; q < NPAIR; q += stride) {
        const int n   = q >> 18;                   // batch index (HWP2 = 2^18)
        const int hw2 = q & (HWP2 - 1);            // pair position within image
        const float2* base = x2 + (size_t)n * (NCH * HWP2) + hw2;

        // Load all 19 channels as float2. The max-tree below consumes ALL v,
        // so ptxas front-batches the 19 LDG.64 (R3/R8/R12-proven invariant).
        float2 v[NCH];
#pragma unroll
        for (int c = 0; c < NCH; c++) {
            v[c] = base[(size_t)c * HWP2];
        }

        // Max via FMNMX tree (depth 5): v[] dies at the subs right after ->
        // next iteration's loads can reuse those registers early (R12 win).
        float tx[10], ty[10];
#pragma unroll
        for (int c = 0; c < 9; c++) {
            tx[c] = fmaxf(v[2 * c].x, v[2 * c + 1].x);
            ty[c] = fmaxf(v[2 * c].y, v[2 * c + 1].y);
        }
        tx[9] = v[18].x; ty[9] = v[18].y;
#pragma unroll
        for (int c = 0; c < 5; c++) {
            tx[c] = fmaxf(tx[c], tx[c + 5]);
            ty[c] = fmaxf(ty[c], ty[c + 5]);
        }
        tx[0] = fmaxf(tx[0], tx[3]); ty[0] = fmaxf(ty[0], ty[3]);
        tx[1] = fmaxf(tx[1], tx[4]); ty[1] = fmaxf(ty[1], ty[4]);
        const float mx = fmaxf(fmaxf(tx[0], tx[1]), tx[2]);
        const float my = fmaxf(fmaxf(ty[0], ty[1]), ty[2]);

        // Exp-sums, packed f32x2: d = v - m (exact, feeds the d==0 idx test),
        // p = d * log2e, e = ex2.approx(p). idx chain gates only the
        // fire-and-forget reductions (off the critical path).
        unsigned long long m2, s1p, s2p;
        asm("mov.b64 %0, {%1, %2};" : "=l"(m2) : "f"(mx), "f"(my));
        asm("mov.b64 %0, {%1, %2};" : "=l"(s1p) : "f"(0.0f), "f"(0.0f));
        asm("mov.b64 %0, {%1, %2};" : "=l"(s2p) : "f"(0.0f), "f"(0.0f));
        int ix = 64, iy = 64;
#pragma unroll
        for (int c = 0; c < NCH; c++) {
            unsigned long long v2c, d2, p2, e2;
            asm("mov.b64 %0, {%1, %2};" : "=l"(v2c) : "f"(v[c].x), "f"(v[c].y));
            asm("sub.rn.f32x2 %0, %1, %2;" : "=l"(d2) : "l"(v2c), "l"(m2));
            float dx, dy;
            asm("mov.b64 {%0, %1}, %2;" : "=f"(dx), "=f"(dy) : "l"(d2));
            ix = min(ix, (dx == 0.0f) ? c : 64);
            iy = min(iy, (dy == 0.0f) ? c : 64);
            asm("mul.rn.f32x2 %0, %1, %2;" : "=l"(p2) : "l"(d2), "l"(L2E2));
            float px, py, ex, ey;
            asm("mov.b64 {%0, %1}, %2;" : "=f"(px), "=f"(py) : "l"(p2));
            asm("ex2.approx.ftz.f32 %0, %1;" : "=f"(ex) : "f"(px));
            asm("ex2.approx.ftz.f32 %0, %1;" : "=f"(ey) : "f"(py));
            asm("mov.b64 %0, {%1, %2};" : "=l"(e2) : "f"(ex), "f"(ey));
            asm("add.rn.f32x2 %0, %1, %2;" : "=l"(s1p) : "l"(s1p), "l"(e2));
            asm("fma.rn.f32x2 %0, %1, %2, %3;" : "=l"(s2p) : "l"(e2), "l"(e2), "l"(s2p));
        }
        float s1x, s1y, s2x, s2y;
        asm("mov.b64 {%0, %1}, %2;" : "=f"(s1x), "=f"(s1y) : "l"(s1p));
        asm("mov.b64 {%0, %1}, %2;" : "=f"(s2x), "=f"(s2y) : "l"(s2p));

        // r in (1/19, 1] (Cauchy-Schwarz) -> fixed-point, pack with count=1,
        // fire-and-forget 64-bit reduction to this CTA's column in L2.
        const unsigned int rvx = __float2uint_rn(__fdividef(s2x, s1x * s1x) * R_SCALE);
        const unsigned int rvy = __float2uint_rn(__fdividef(s2y, s1y * s1y) * R_SCALE);
        atomicAdd(&g_bins[ix][blockIdx.x], CNT_ONE + (unsigned long long)rvx);
        atomicAdd(&g_bins[iy][blockIdx.x], CNT_ONE + (unsigned long long)rvy);
    }

    // ---- fused finalize: last block reduces the per-CTA bins ----
    __threadfence();                               // order REDs before ticket
    __shared__ unsigned int s_last;
    __shared__ float        s_cls[NCH];
    if (t == 0) {
        unsigned int ticket = atomicAdd(&g_done, 1u);
        s_last = (ticket == GRID_BLOCKS - 1) ? 1u : 0u;
    }
    __syncthreads();
    if (s_last) {
        const int w    = t >> 5;                   // 8 warps
        const int lane = t & 31;
        // Warp w reduces classes w, w+8, w+16. Packed u64 values add
        // directly (sum bits can't carry into cnt bits: max sum = 2^41).
        for (int c = w; c < NCH; c += 8) {
            unsigned long long acc = 0ULL;
            for (int j = lane; j < GRID_BLOCKS; j += 32)
                acc += __ldcg(&g_bins[c][j]);
#pragma unroll
            for (int o = 16; o > 0; o >>= 1)
                acc += __shfl_down_sync(0xffffffffu, acc, o);
            if (lane == 0) {
                const float cnt = (float)(unsigned int)(acc >> 42);
                const float sum = (float)(acc & SUM_MASK) * (1.0f / R_SCALE);
                const float scale = powf((float)NPIX, 1.0f - IW_F);        // Np^0.8
                const float den   = fmaxf(powf(cnt, IW_F) * scale, 1.0f);
                s_cls[c] = sum / den;
            }
        }
        __syncthreads();                           // all bin reads done
        // Re-zero bins for the next graph replay.
        unsigned long long* flat = &g_bins[0][0];
        for (int i = t; i < NCH * GRID_BLOCKS; i += 256)
            flat[i] = 0ULL;
        // Final 19-term sum.
        if (t < 32) {
            float p = (t < NCH) ? s_cls[t] : 0.0f;
#pragma unroll
            for (int o = 16; o > 0; o >>= 1)
                p += __shfl_down_sync(0xffffffffu, p, o);
            if (t == 0) {
                out[0] = -p / (float)(NBAT * NCH);
                g_done = 0;                        // reset ticket
            }
        }
    }
}

extern "C" void kernel_launch(void* const* d_in, const int* in_sizes, int n_in,
                              void* d_out, int out_size) {
    (void)in_sizes; (void)n_in; (void)out_size;
    const float2* x2 = (const float2*)d_in[0];
    float* out = (float*)d_out;

    // Single launch, one exact wave: 740 CTAs x 256 threads, 5 CTAs/SM.
    // R12 compute skeleton; binning moved off the SM LSU: packed u64
    // (cnt<<42 | r*2^20) fire-and-forget red.add to per-CTA L2 bins.
    msiw_kernel<<<GRID_BLOCKS, 256>>>(x2, out);
}

// round 17
// speedup vs baseline: 1.6763x; 1.6763x over previous
#include <cuda_runtime.h>
#include <cuda_bf16.h>

// Problem constants: nw_out is [N=4, C=19, H=512, W=1024] float32.
#define NCH    19
#define NBAT   4
#define HH     512
#define WW     1024
#define HWP    (HH * WW)            // 524288 pixels per image
#define HWP2   (HWP / 2)            // 262144 float2 pairs per image-channel
#define NPIX   (NBAT * HWP)         // 2097152
#define NPAIR  (NPIX / 2)           // 1048576
#define IW_F   0.2f
#define BLOCK_T     256
#define GRID_BLOCKS 592             // 4 CTAs/SM x 148 SMs (smem: 4 x 39KB)
#define STRIDE      (GRID_BLOCKS * BLOCK_T)      // 151552
#define ROUNDS      7               // ceil(NPAIR / STRIDE) = ceil(6.92)

// Scratch accumulators. Zeroed at module load; fused finalize re-zeroes them.
__device__ float        g_sum[NCH] = {};
__device__ unsigned int g_cnt[NCH] = {};
__device__ unsigned int g_done     = 0;

__device__ __forceinline__ unsigned int smem_u32(const void* p) {
    unsigned int a;
    asm("{ .reg .u64 t; cvta.to.shared.u64 t, %1; cvt.u32.u64 %0, t; }"
        : "=r"(a) : "l"(p));
    return a;
}

__global__ __launch_bounds__(BLOCK_T, 4) void msiw_kernel(const float2* __restrict__ x2,
                                                          float* __restrict__ out) {
    // Thread-private prefetch slots: buf[c][t]. cp.async groups are PER-THREAD
    // state, so no __syncthreads is needed anywhere in the main loop.
    __shared__ float2       buf[NCH][BLOCK_T];    // 38912 B
    __shared__ float        s_sum[NCH];
    __shared__ unsigned int s_cnt[NCH];

    const int t = threadIdx.x;
    if (t < NCH) { s_sum[t] = 0.0f; s_cnt[t] = 0u; }
    __syncthreads();

    const unsigned int sb = smem_u32(&buf[0][0]);

    // Prefetch one round's 19 float2 for THIS thread into its slots.
    auto prefetch = [&](int qp) {
        const int qc  = qp < (NPAIR - 1) ? qp : (NPAIR - 1);   // clamp (valid addr)
        const int n   = qc >> 18;                              // HWP2 = 2^18
        const int hw2 = qc & (HWP2 - 1);
        const float2* base = x2 + (size_t)n * (NCH * HWP2) + hw2;
#pragma unroll
        for (int c = 0; c < NCH; c++) {
            const unsigned int dst = sb + (unsigned int)((c * BLOCK_T + t) * 8);
            // "memory" clobber: keeps this AFTER this round's LDS reads at
            // compile time. At runtime the DMA write-back arrives >=~500cyc
            // later (always DRAM-sourced), far after the ~60cyc LDS drain.
            asm volatile("cp.async.ca.shared.global [%0], [%1], 8;"
                         :: "r"(dst), "l"(base + (size_t)c * HWP2) : "memory");
        }
        asm volatile("cp.async.commit_group;" ::: "memory");
    };

    // Packed log2(e) for the exp conversion.
    unsigned long long L2E2;
    asm("mov.b64 %0, {%1, %2};" : "=l"(L2E2)
        : "f"(1.4426950408889634f), "f"(1.4426950408889634f));

    int q = blockIdx.x * BLOCK_T + t;
    prefetch(q);                                   // prologue (only exposed mem)

#pragma unroll 1
    for (int r = 0; r < ROUNDS; r++) {
        asm volatile("cp.async.wait_group 0;" ::: "memory");

        // Pull this thread's 19 channel pairs from smem (conflict-free LDS.64:
        // lanes are consecutive within buf[c][.]).
        float2 v[NCH];
#pragma unroll
        for (int c = 0; c < NCH; c++) v[c] = buf[c][t];

        // Kick next round's prefetch NOW so it streams from DRAM during the
        // whole compute phase below (this is the mem/compute overlap).
        if (r + 1 < ROUNDS) prefetch(q + STRIDE);

        // ---- R12-proven compute core ----
        float tx[10], ty[10];
#pragma unroll
        for (int c = 0; c < 9; c++) {
            tx[c] = fmaxf(v[2 * c].x, v[2 * c + 1].x);
            ty[c] = fmaxf(v[2 * c].y, v[2 * c + 1].y);
        }
        tx[9] = v[18].x; ty[9] = v[18].y;
#pragma unroll
        for (int c = 0; c < 5; c++) {
            tx[c] = fmaxf(tx[c], tx[c + 5]);
            ty[c] = fmaxf(ty[c], ty[c + 5]);
        }
        tx[0] = fmaxf(tx[0], tx[3]); ty[0] = fmaxf(ty[0], ty[3]);
        tx[1] = fmaxf(tx[1], tx[4]); ty[1] = fmaxf(ty[1], ty[4]);
        const float mx = fmaxf(fmaxf(tx[0], tx[1]), tx[2]);
        const float my = fmaxf(fmaxf(ty[0], ty[1]), ty[2]);

        unsigned long long m2, s1p, s2p;
        asm("mov.b64 %0, {%1, %2};" : "=l"(m2) : "f"(mx), "f"(my));
        asm("mov.b64 %0, {%1, %2};" : "=l"(s1p) : "f"(0.0f), "f"(0.0f));
        asm("mov.b64 %0, {%1, %2};" : "=l"(s2p) : "f"(0.0f), "f"(0.0f));
        int ix = 64, iy = 64;
#pragma unroll
        for (int c = 0; c < NCH; c++) {
            unsigned long long v2c, d2, p2, e2;
            asm("mov.b64 %0, {%1, %2};" : "=l"(v2c) : "f"(v[c].x), "f"(v[c].y));
            asm("sub.rn.f32x2 %0, %1, %2;" : "=l"(d2) : "l"(v2c), "l"(m2));
            float dx, dy;
            asm("mov.b64 {%0, %1}, %2;" : "=f"(dx), "=f"(dy) : "l"(d2));
            ix = min(ix, (dx == 0.0f) ? c : 64);   // FMNMX returns input exactly
            iy = min(iy, (dy == 0.0f) ? c : 64);
            asm("mul.rn.f32x2 %0, %1, %2;" : "=l"(p2) : "l"(d2), "l"(L2E2));
            float px, py, ex, ey;
            asm("mov.b64 {%0, %1}, %2;" : "=f"(px), "=f"(py) : "l"(p2));
            asm("ex2.approx.ftz.f32 %0, %1;" : "=f"(ex) : "f"(px));
            asm("ex2.approx.ftz.f32 %0, %1;" : "=f"(ey) : "f"(py));
            asm("mov.b64 %0, {%1, %2};" : "=l"(e2) : "f"(ex), "f"(ey));
            asm("add.rn.f32x2 %0, %1, %2;" : "=l"(s1p) : "l"(s1p), "l"(e2));
            asm("fma.rn.f32x2 %0, %1, %2, %3;" : "=l"(s2p) : "l"(e2), "l"(e2), "l"(s2p));
        }
        float s1x, s1y, s2x, s2y;
        asm("mov.b64 {%0, %1}, %2;" : "=f"(s1x), "=f"(s1y) : "l"(s1p));
        asm("mov.b64 {%0, %1}, %2;" : "=f"(s2x), "=f"(s2y) : "l"(s2p));

        if (q < NPAIR) {
            atomicAdd(&s_sum[ix], __fdividef(s2x, s1x * s1x));
            atomicAdd(&s_sum[iy], __fdividef(s2y, s1y * s1y));
            atomicAdd(&s_cnt[ix], 1u);
            atomicAdd(&s_cnt[iy], 1u);
        }
        q += STRIDE;
    }

    __syncthreads();
    if (t < NCH) {
        atomicAdd(&g_sum[t], s_sum[t]);
        atomicAdd(&g_cnt[t], s_cnt[t]);
    }

    // ---- fused finalize: last block does the 19-term reduction ----
    __threadfence();
    __shared__ unsigned int s_last;
    if (t == 0) {
        unsigned int ticket = atomicAdd(&g_done, 1u);
        s_last = (ticket == GRID_BLOCKS - 1) ? 1u : 0u;
    }
    __syncthreads();
    if (s_last && t < 32) {
        int c = t;
        float partial = 0.0f;
        if (c < NCH) {
            float cnt   = (float)g_cnt[c];
            float scale = powf((float)NPIX, 1.0f - IW_F);        // Np^0.8
            float den   = fmaxf(powf(cnt, IW_F) * scale, 1.0f);  // max(hist^0.2*Np^0.8, 1)
            partial = g_sum[c] / den;
            g_sum[c] = 0.0f;                                     // reset for next replay
            g_cnt[c] = 0u;
        }
#pragma unroll
        for (int o = 16; o > 0; o >>= 1)
            partial += __shfl_down_sync(0xffffffffu, partial, o);
        if (c == 0) {
            out[0] = -partial / (float)(NBAT * NCH);
            g_done = 0;                                          // reset ticket
        }
    }
}

extern "C" void kernel_launch(void* const* d_in, const int* in_sizes, int n_in,
                              void* d_out, int out_size) {
    (void)in_sizes; (void)n_in; (void)out_size;
    const float2* x2 = (const float2*)d_in[0];
    float* out = (float*)d_out;

    // Single launch: 592 CTAs x 256 threads, 4 CTAs/SM (39KB smem each).
    // Thread-private cp.async prefetch (no barriers in the loop) hides DRAM
    // behind the compute phase. Finalize fused via the last-block ticket.
    msiw_kernel<<<GRID_BLOCKS, BLOCK_T>>>(x2, out);
}